// round 7
// baseline (speedup 1.0000x reference)
#include <cuda_runtime.h>
#include <cuda_bf16.h>
#include <cstdint>

// Problem constants
#define NB 16
#define CC 512
#define NN 2304      // 48*48
#define II 64        // inter channels

// Tiling
#define BM 128
#define BN 128
#define BK 16
#define PAD 8        // BN+PAD = 136 floats; 136*4 = 544 = 16*34 -> 16B-aligned rows

// ---------------------------------------------------------------------------
// Scratch (device globals: allocation-free per harness rules)
// ---------------------------------------------------------------------------
__device__ float g_qk[(size_t)NB * 128 * NN];       // rows 0..63 = q, 64..127 = k
__device__ float g_v [(size_t)NB * CC  * NN];       // v projection
__device__ float g_s [(size_t)NB * NN  * NN];       // attention logits / probs

// ---------------------------------------------------------------------------
// Shared 8x8-microtile compute stage (BMxBN tile, one BK slab)
// ---------------------------------------------------------------------------
__device__ __forceinline__ void mm_compute(const float (*As)[BM + PAD],
                                           const float (*Bs)[BN + PAD],
                                           float acc[8][8], int tr, int tc) {
#pragma unroll
    for (int kk = 0; kk < BK; kk++) {
        float ra[8], rb[8];
#pragma unroll
        for (int r = 0; r < 8; r++) ra[r] = As[kk][tr * 8 + r];
#pragma unroll
        for (int c = 0; c < 8; c++) rb[c] = Bs[kk][tc * 8 + c];
#pragma unroll
        for (int r = 0; r < 8; r++)
#pragma unroll
            for (int c = 0; c < 8; c++)
                acc[r][c] += ra[r] * rb[c];
    }
}

// ---------------------------------------------------------------------------
// 1) q/k projection: g_qk[b][i][n] = sum_c [Wq;Wk][i][c] * x[b][c][n]
//    grid (NN/BN, 1, NB), block 256.  M = 128 exactly (64 q rows + 64 k rows)
// ---------------------------------------------------------------------------
__global__ void __launch_bounds__(256)
k_qk(const float* __restrict__ x, const float* __restrict__ Wq,
     const float* __restrict__ Wk) {
    __shared__ float As[BK][BM + PAD];
    __shared__ float Bs[BK][BN + PAD];

    const int tid = threadIdx.x;
    const int n0 = blockIdx.x * BN;
    const int b  = blockIdx.z;
    const int tr = tid / 16, tc = tid % 16;

    float acc[8][8];
#pragma unroll
    for (int r = 0; r < 8; r++)
#pragma unroll
        for (int c = 0; c < 8; c++) acc[r][c] = 0.f;

    const float* xb = x + (size_t)b * CC * NN;

    for (int k0 = 0; k0 < CC; k0 += BK) {
        // A = [Wq;Wk] (M=128 x K=512), transpose into As[kk][mm]
        for (int i = tid; i < BM * BK; i += 256) {
            int mm = i / BK, kk = i % BK;
            const float* Wp = (mm < II) ? (Wq + (size_t)mm * CC)
                                        : (Wk + (size_t)(mm - II) * CC);
            As[kk][mm] = Wp[k0 + kk];
        }
        // B = x[b] (K x N), direct
        for (int i = tid; i < BK * BN; i += 256) {
            int kk = i / BN, nn = i % BN;
            Bs[kk][nn] = xb[(size_t)(k0 + kk) * NN + n0 + nn];
        }
        __syncthreads();
        mm_compute(As, Bs, acc, tr, tc);
        __syncthreads();
    }

    float* outb = g_qk + (size_t)b * 128 * NN;
#pragma unroll
    for (int r = 0; r < 8; r++) {
        size_t base = (size_t)(tr * 8 + r) * NN + n0 + tc * 8;
        *(float4*)(outb + base)     = make_float4(acc[r][0], acc[r][1], acc[r][2], acc[r][3]);
        *(float4*)(outb + base + 4) = make_float4(acc[r][4], acc[r][5], acc[r][6], acc[r][7]);
    }
}

// ---------------------------------------------------------------------------
// 2) v projection: g_v[b][o][n] = sum_c Wv[o][c] * x[b][c][n]
//    grid (NN/BN, CC/BM, NB)
// ---------------------------------------------------------------------------
__global__ void __launch_bounds__(256)
k_v(const float* __restrict__ x, const float* __restrict__ Wv) {
    __shared__ float As[BK][BM + PAD];
    __shared__ float Bs[BK][BN + PAD];

    const int tid = threadIdx.x;
    const int n0 = blockIdx.x * BN;
    const int m0 = blockIdx.y * BM;
    const int b  = blockIdx.z;
    const int tr = tid / 16, tc = tid % 16;

    float acc[8][8];
#pragma unroll
    for (int r = 0; r < 8; r++)
#pragma unroll
        for (int c = 0; c < 8; c++) acc[r][c] = 0.f;

    const float* xb = x + (size_t)b * CC * NN;

    for (int k0 = 0; k0 < CC; k0 += BK) {
        for (int i = tid; i < BM * BK; i += 256) {
            int mm = i / BK, kk = i % BK;
            As[kk][mm] = Wv[(size_t)(m0 + mm) * CC + k0 + kk];
        }
        for (int i = tid; i < BK * BN; i += 256) {
            int kk = i / BN, nn = i % BN;
            Bs[kk][nn] = xb[(size_t)(k0 + kk) * NN + n0 + nn];
        }
        __syncthreads();
        mm_compute(As, Bs, acc, tr, tc);
        __syncthreads();
    }

    float* outb = g_v + (size_t)b * CC * NN;
#pragma unroll
    for (int r = 0; r < 8; r++) {
        size_t base = (size_t)(m0 + tr * 8 + r) * NN + n0 + tc * 8;
        *(float4*)(outb + base)     = make_float4(acc[r][0], acc[r][1], acc[r][2], acc[r][3]);
        *(float4*)(outb + base + 4) = make_float4(acc[r][4], acc[r][5], acc[r][6], acc[r][7]);
    }
}

// ---------------------------------------------------------------------------
// 3) logits: g_s[b][n][m] = sum_i q[b][i][n] * k[b][i][m]
//    A and B are both stored K-major in g_qk -> direct (coalesced) loads.
//    grid (NN/BN [m], NN/BM [n], NB)
// ---------------------------------------------------------------------------
__global__ void __launch_bounds__(256)
k_s() {
    __shared__ float As[BK][BM + PAD];
    __shared__ float Bs[BK][BN + PAD];

    const int tid = threadIdx.x;
    const int n0 = blockIdx.x * BN;   // key (m) tile
    const int m0 = blockIdx.y * BM;   // query (n) tile
    const int b  = blockIdx.z;
    const int tr = tid / 16, tc = tid % 16;

    float acc[8][8];
#pragma unroll
    for (int r = 0; r < 8; r++)
#pragma unroll
        for (int c = 0; c < 8; c++) acc[r][c] = 0.f;

    const float* qb = g_qk + (size_t)b * 128 * NN;        // rows [0,64): q
    const float* kb = qb + (size_t)II * NN;               // rows [64,128): k

    for (int k0 = 0; k0 < II; k0 += BK) {
        for (int i = tid; i < BK * BM; i += 256) {
            int kk = i / BM, mm = i % BM;
            As[kk][mm] = qb[(size_t)(k0 + kk) * NN + m0 + mm];
        }
        for (int i = tid; i < BK * BN; i += 256) {
            int kk = i / BN, nn = i % BN;
            Bs[kk][nn] = kb[(size_t)(k0 + kk) * NN + n0 + nn];
        }
        __syncthreads();
        mm_compute(As, Bs, acc, tr, tc);
        __syncthreads();
    }

    float* sb = g_s + (size_t)b * NN * NN;
#pragma unroll
    for (int r = 0; r < 8; r++) {
        size_t base = (size_t)(m0 + tr * 8 + r) * NN + n0 + tc * 8;
        *(float4*)(sb + base)     = make_float4(acc[r][0], acc[r][1], acc[r][2], acc[r][3]);
        *(float4*)(sb + base + 4) = make_float4(acc[r][4], acc[r][5], acc[r][6], acc[r][7]);
    }
}

// ---------------------------------------------------------------------------
// 4) softmax over last dim of g_s (row length NN = 9*256), in place
//    grid (NB*NN), block 256
// ---------------------------------------------------------------------------
__global__ void __launch_bounds__(256)
k_softmax() {
    const int tid = threadIdx.x;
    float* s = g_s + (size_t)blockIdx.x * NN;

    float v[9];
    float mx = -1e30f;
#pragma unroll
    for (int j = 0; j < 9; j++) {
        v[j] = s[tid + j * 256];
        mx = fmaxf(mx, v[j]);
    }
#pragma unroll
    for (int o = 16; o > 0; o >>= 1)
        mx = fmaxf(mx, __shfl_xor_sync(0xFFFFFFFFu, mx, o));

    __shared__ float redm[8];
    __shared__ float reds[8];
    if ((tid & 31) == 0) redm[tid >> 5] = mx;
    __syncthreads();
    float m2 = redm[0];
#pragma unroll
    for (int w = 1; w < 8; w++) m2 = fmaxf(m2, redm[w]);

    float sum = 0.f;
#pragma unroll
    for (int j = 0; j < 9; j++) {
        v[j] = __expf(v[j] - m2);
        sum += v[j];
    }
#pragma unroll
    for (int o = 16; o > 0; o >>= 1)
        sum += __shfl_xor_sync(0xFFFFFFFFu, sum, o);
    if ((tid & 31) == 0) reds[tid >> 5] = sum;
    __syncthreads();
    float tot = 0.f;
#pragma unroll
    for (int w = 0; w < 8; w++) tot += reds[w];

    const float inv = 1.0f / tot;
#pragma unroll
    for (int j = 0; j < 9; j++)
        s[tid + j * 256] = v[j] * inv;
}

// ---------------------------------------------------------------------------
// 5) out[b][c][n] = gamma * sum_m v[b][c][m] * P[b][n][m] + x[b][c][n]
//    GEMM: M-dim=c, N-dim=n, K-dim=m.  Both A (v) and B (P, transposed use)
//    are K-contiguous in memory -> transpose-load into shared.
//    grid (NN/BN, CC/BM, NB)
// ---------------------------------------------------------------------------
__global__ void __launch_bounds__(256)
k_out(const float* __restrict__ x, const float* __restrict__ gamma,
      float* __restrict__ out) {
    __shared__ float As[BK][BM + PAD];
    __shared__ float Bs[BK][BN + PAD];

    const int tid = threadIdx.x;
    const int n0 = blockIdx.x * BN;
    const int c0 = blockIdx.y * BM;
    const int b  = blockIdx.z;
    const int tr = tid / 16, tc = tid % 16;

    float acc[8][8];
#pragma unroll
    for (int r = 0; r < 8; r++)
#pragma unroll
        for (int c = 0; c < 8; c++) acc[r][c] = 0.f;

    const float* vb = g_v + (size_t)b * CC * NN;
    const float* pb = g_s + (size_t)b * NN * NN;

    for (int k0 = 0; k0 < NN; k0 += BK) {
        // A = v[b]: rows c, cols m (contiguous) -> transpose into As[kk][cc]
        for (int i = tid; i < BM * BK; i += 256) {
            int mm = i / BK, kk = i % BK;
            As[kk][mm] = vb[(size_t)(c0 + mm) * NN + k0 + kk];
        }
        // B = P^T: Bs[kk(m)][nn(n)] = P[n0+nn][k0+kk] (m contiguous)
        for (int i = tid; i < BN * BK; i += 256) {
            int nn = i / BK, kk = i % BK;
            Bs[kk][nn] = pb[(size_t)(n0 + nn) * NN + k0 + kk];
        }
        __syncthreads();
        mm_compute(As, Bs, acc, tr, tc);
        __syncthreads();
    }

    const float g = gamma[0];
    const float* xb = x + (size_t)b * CC * NN;
    float* ob = out + (size_t)b * CC * NN;
#pragma unroll
    for (int r = 0; r < 8; r++) {
        size_t base = (size_t)(c0 + tr * 8 + r) * NN + n0 + tc * 8;
        float4 x0 = *(const float4*)(xb + base);
        float4 x1 = *(const float4*)(xb + base + 4);
        float4 o0 = make_float4(g * acc[r][0] + x0.x, g * acc[r][1] + x0.y,
                                g * acc[r][2] + x0.z, g * acc[r][3] + x0.w);
        float4 o1 = make_float4(g * acc[r][4] + x1.x, g * acc[r][5] + x1.y,
                                g * acc[r][6] + x1.z, g * acc[r][7] + x1.w);
        *(float4*)(ob + base)     = o0;
        *(float4*)(ob + base + 4) = o1;
    }
}

// ---------------------------------------------------------------------------
// Entry point: 5 sequential kernel launches, graph-capturable, no allocs.
// Inputs (metadata order): x, Wq, Wk, Wv, gamma. Output: float32 (B,C,H,W).
// ---------------------------------------------------------------------------
extern "C" void kernel_launch(void* const* d_in, const int* in_sizes, int n_in,
                              void* d_out, int out_size) {
    const float* x     = (const float*)d_in[0];
    const float* Wq    = (const float*)d_in[1];
    const float* Wk    = (const float*)d_in[2];
    const float* Wv    = (const float*)d_in[3];
    const float* gamma = (const float*)d_in[4];
    float* out = (float*)d_out;

    k_qk<<<dim3(NN / BN, 1, NB), 256>>>(x, Wq, Wk);
    k_v <<<dim3(NN / BN, CC / BM, NB), 256>>>(x, Wv);
    k_s <<<dim3(NN / BN, NN / BM, NB), 256>>>();
    k_softmax<<<NB * NN, 256>>>();
    k_out<<<dim3(NN / BN, CC / BM, NB), 256>>>(x, gamma, out);
}

// round 8
// speedup vs baseline: 1.9214x; 1.9214x over previous
#include <cuda_runtime.h>
#include <cuda_bf16.h>
#include <cstdint>

// Problem constants
#define NB 16
#define CC 512
#define NN 2304      // 48*48
#define II 64        // inter channels

// fp32 tiling (k_qk, k_s)
#define BM 128
#define BN 128
#define BK 16
#define PAD 8

// tf32 mma tiling (k_v, k_out)
#define TBK 32
#define BKP 36       // padded k-stride (uints): 36 mod 32 = 4 -> conflict-free frags

// ---------------------------------------------------------------------------
// Scratch (device globals: allocation-free per harness rules)
// ---------------------------------------------------------------------------
__device__ float g_qk[(size_t)NB * 128 * NN];       // rows 0..63 = q, 64..127 = k
__device__ float g_v [(size_t)NB * CC  * NN];       // v projection
__device__ float g_s [(size_t)NB * NN  * NN];       // attention logits / probs

// ---------------------------------------------------------------------------
// tf32 helpers
// ---------------------------------------------------------------------------
__device__ __forceinline__ uint32_t f2tf32(float f) {
    uint32_t r;
    asm("cvt.rna.tf32.f32 %0, %1;" : "=r"(r) : "f"(f));
    return r;
}

__device__ __forceinline__ void mma_tf32(float c[4], const uint32_t a[4],
                                         const uint32_t b[2]) {
    asm volatile(
        "mma.sync.aligned.m16n8k8.row.col.f32.tf32.tf32.f32 "
        "{%0,%1,%2,%3}, {%4,%5,%6,%7}, {%8,%9}, {%0,%1,%2,%3};"
        : "+f"(c[0]), "+f"(c[1]), "+f"(c[2]), "+f"(c[3])
        : "r"(a[0]), "r"(a[1]), "r"(a[2]), "r"(a[3]),
          "r"(b[0]), "r"(b[1]));
}

// Shared mma mainloop stage for one TBK slab already resident in smem.
// Warp tile: 32 (m) x 64 (n) -> 2 m-frags x 8 n-frags.
__device__ __forceinline__ void mma_stage(const uint32_t* __restrict__ As,
                                          const uint32_t* __restrict__ Bs,
                                          float acc[2][8][4],
                                          int wm, int wn, int gid, int tig) {
#pragma unroll
    for (int ks = 0; ks < TBK; ks += 8) {
        uint32_t a[2][4], bf[8][2];
#pragma unroll
        for (int mf = 0; mf < 2; mf++) {
            int r = (wm * 32 + mf * 16 + gid) * BKP + ks + tig;
            a[mf][0] = As[r];
            a[mf][1] = As[r + 8 * BKP];
            a[mf][2] = As[r + 4];
            a[mf][3] = As[r + 8 * BKP + 4];
        }
#pragma unroll
        for (int nf = 0; nf < 8; nf++) {
            int r = (wn * 64 + nf * 8 + gid) * BKP + ks + tig;
            bf[nf][0] = Bs[r];
            bf[nf][1] = Bs[r + 4];
        }
#pragma unroll
        for (int mf = 0; mf < 2; mf++)
#pragma unroll
            for (int nf = 0; nf < 8; nf++)
                mma_tf32(acc[mf][nf], a[mf], bf[nf]);
    }
}

// ---------------------------------------------------------------------------
// fp32 8x8-microtile compute stage (k_qk, k_s)
// ---------------------------------------------------------------------------
__device__ __forceinline__ void mm_compute(const float (*As)[BM + PAD],
                                           const float (*Bs)[BN + PAD],
                                           float acc[8][8], int tr, int tc) {
#pragma unroll
    for (int kk = 0; kk < BK; kk++) {
        float ra[8], rb[8];
#pragma unroll
        for (int r = 0; r < 8; r++) ra[r] = As[kk][tr * 8 + r];
#pragma unroll
        for (int c = 0; c < 8; c++) rb[c] = Bs[kk][tc * 8 + c];
#pragma unroll
        for (int r = 0; r < 8; r++)
#pragma unroll
            for (int c = 0; c < 8; c++)
                acc[r][c] += ra[r] * rb[c];
    }
}

// ---------------------------------------------------------------------------
// 1) q/k projection (fp32 — feeds softmax, keep exact)
// ---------------------------------------------------------------------------
__global__ void __launch_bounds__(256)
k_qk(const float* __restrict__ x, const float* __restrict__ Wq,
     const float* __restrict__ Wk) {
    __shared__ float As[BK][BM + PAD];
    __shared__ float Bs[BK][BN + PAD];

    const int tid = threadIdx.x;
    const int n0 = blockIdx.x * BN;
    const int b  = blockIdx.z;
    const int tr = tid / 16, tc = tid % 16;

    float acc[8][8];
#pragma unroll
    for (int r = 0; r < 8; r++)
#pragma unroll
        for (int c = 0; c < 8; c++) acc[r][c] = 0.f;

    const float* xb = x + (size_t)b * CC * NN;

    for (int k0 = 0; k0 < CC; k0 += BK) {
        for (int i = tid; i < BM * BK; i += 256) {
            int mm = i / BK, kk = i % BK;
            const float* Wp = (mm < II) ? (Wq + (size_t)mm * CC)
                                        : (Wk + (size_t)(mm - II) * CC);
            As[kk][mm] = Wp[k0 + kk];
        }
        for (int i = tid; i < BK * BN; i += 256) {
            int kk = i / BN, nn = i % BN;
            Bs[kk][nn] = xb[(size_t)(k0 + kk) * NN + n0 + nn];
        }
        __syncthreads();
        mm_compute(As, Bs, acc, tr, tc);
        __syncthreads();
    }

    float* outb = g_qk + (size_t)b * 128 * NN;
#pragma unroll
    for (int r = 0; r < 8; r++) {
        size_t base = (size_t)(tr * 8 + r) * NN + n0 + tc * 8;
        *(float4*)(outb + base)     = make_float4(acc[r][0], acc[r][1], acc[r][2], acc[r][3]);
        *(float4*)(outb + base + 4) = make_float4(acc[r][4], acc[r][5], acc[r][6], acc[r][7]);
    }
}

// ---------------------------------------------------------------------------
// 2) v projection (tf32 tensor core): g_v[b][o][n] = sum_c Wv[o][c] * x[b][c][n]
//    grid (NN/128, CC/128, NB), 256 threads (8 warps, 4x2).
// ---------------------------------------------------------------------------
__global__ void __launch_bounds__(256)
k_v(const float* __restrict__ x, const float* __restrict__ Wv) {
    __shared__ uint32_t As[128 * BKP];
    __shared__ uint32_t Bs[128 * BKP];

    const int tid = threadIdx.x;
    const int n0 = blockIdx.x * 128;
    const int m0 = blockIdx.y * 128;
    const int b  = blockIdx.z;

    const int lane = tid & 31;
    const int gid  = lane >> 2;
    const int tig  = lane & 3;
    const int warp = tid >> 5;
    const int wm   = warp >> 1;   // 0..3
    const int wn   = warp & 1;    // 0..1

    float acc[2][8][4];
#pragma unroll
    for (int mf = 0; mf < 2; mf++)
#pragma unroll
        for (int nf = 0; nf < 8; nf++)
#pragma unroll
            for (int i = 0; i < 4; i++) acc[mf][nf][i] = 0.f;

    const float* xb = x + (size_t)b * CC * NN;

    for (int k0 = 0; k0 < CC; k0 += TBK) {
        // A = Wv rows (k contiguous): 128 x 32 = 1024 float4
        for (int t = tid; t < 1024; t += 256) {
            int mm = t >> 3, k4 = (t & 7) << 2;
            float4 f = *(const float4*)(Wv + (size_t)(m0 + mm) * CC + k0 + k4);
            uint32_t* p = &As[mm * BKP + k4];
            p[0] = f2tf32(f.x); p[1] = f2tf32(f.y);
            p[2] = f2tf32(f.z); p[3] = f2tf32(f.w);
        }
        // B = x (c-major x n): transpose-gather Bs[nn][kk] = x[k0+kk][n0+nn]
        for (int t = tid; t < TBK * 128; t += 256) {
            int kk = t >> 7, nn = t & 127;
            Bs[nn * BKP + kk] = f2tf32(xb[(size_t)(k0 + kk) * NN + n0 + nn]);
        }
        __syncthreads();
        mma_stage(As, Bs, acc, wm, wn, gid, tig);
        __syncthreads();
    }

    float* outb = g_v + (size_t)b * CC * NN;
#pragma unroll
    for (int mf = 0; mf < 2; mf++)
#pragma unroll
        for (int nf = 0; nf < 8; nf++) {
            int o = m0 + wm * 32 + mf * 16 + gid;
            int n = n0 + wn * 64 + nf * 8 + tig * 2;
            size_t i0 = (size_t)o * NN + n;
            *(float2*)(outb + i0) = make_float2(acc[mf][nf][0], acc[mf][nf][1]);
            size_t i1 = i0 + (size_t)8 * NN;
            *(float2*)(outb + i1) = make_float2(acc[mf][nf][2], acc[mf][nf][3]);
        }
}

// ---------------------------------------------------------------------------
// 3) logits (fp32 — softmax amplifies errors here, keep exact)
// ---------------------------------------------------------------------------
__global__ void __launch_bounds__(256)
k_s() {
    __shared__ float As[BK][BM + PAD];
    __shared__ float Bs[BK][BN + PAD];

    const int tid = threadIdx.x;
    const int n0 = blockIdx.x * BN;   // key (m) tile
    const int m0 = blockIdx.y * BM;   // query (n) tile
    const int b  = blockIdx.z;
    const int tr = tid / 16, tc = tid % 16;

    float acc[8][8];
#pragma unroll
    for (int r = 0; r < 8; r++)
#pragma unroll
        for (int c = 0; c < 8; c++) acc[r][c] = 0.f;

    const float* qb = g_qk + (size_t)b * 128 * NN;
    const float* kb = qb + (size_t)II * NN;

    for (int k0 = 0; k0 < II; k0 += BK) {
        for (int i = tid; i < BK * BM; i += 256) {
            int kk = i / BM, mm = i % BM;
            As[kk][mm] = qb[(size_t)(k0 + kk) * NN + m0 + mm];
        }
        for (int i = tid; i < BK * BN; i += 256) {
            int kk = i / BN, nn = i % BN;
            Bs[kk][nn] = kb[(size_t)(k0 + kk) * NN + n0 + nn];
        }
        __syncthreads();
        mm_compute(As, Bs, acc, tr, tc);
        __syncthreads();
    }

    float* sb = g_s + (size_t)b * NN * NN;
#pragma unroll
    for (int r = 0; r < 8; r++) {
        size_t base = (size_t)(m0 + tr * 8 + r) * NN + n0 + tc * 8;
        *(float4*)(sb + base)     = make_float4(acc[r][0], acc[r][1], acc[r][2], acc[r][3]);
        *(float4*)(sb + base + 4) = make_float4(acc[r][4], acc[r][5], acc[r][6], acc[r][7]);
    }
}

// ---------------------------------------------------------------------------
// 4) softmax over last dim of g_s, in place (DRAM-bound, at roofline)
// ---------------------------------------------------------------------------
__global__ void __launch_bounds__(256)
k_softmax() {
    const int tid = threadIdx.x;
    float* s = g_s + (size_t)blockIdx.x * NN;

    float v[9];
    float mx = -1e30f;
#pragma unroll
    for (int j = 0; j < 9; j++) {
        v[j] = s[tid + j * 256];
        mx = fmaxf(mx, v[j]);
    }
#pragma unroll
    for (int o = 16; o > 0; o >>= 1)
        mx = fmaxf(mx, __shfl_xor_sync(0xFFFFFFFFu, mx, o));

    __shared__ float redm[8];
    __shared__ float reds[8];
    if ((tid & 31) == 0) redm[tid >> 5] = mx;
    __syncthreads();
    float m2 = redm[0];
#pragma unroll
    for (int w = 1; w < 8; w++) m2 = fmaxf(m2, redm[w]);

    float sum = 0.f;
#pragma unroll
    for (int j = 0; j < 9; j++) {
        v[j] = __expf(v[j] - m2);
        sum += v[j];
    }
#pragma unroll
    for (int o = 16; o > 0; o >>= 1)
        sum += __shfl_xor_sync(0xFFFFFFFFu, sum, o);
    if ((tid & 31) == 0) reds[tid >> 5] = sum;
    __syncthreads();
    float tot = 0.f;
#pragma unroll
    for (int w = 0; w < 8; w++) tot += reds[w];

    const float inv = 1.0f / tot;
#pragma unroll
    for (int j = 0; j < 9; j++)
        s[tid + j * 256] = v[j] * inv;
}

// ---------------------------------------------------------------------------
// 5) out GEMM (tf32 tensor core):
//    out[b][c][n] = gamma * sum_m v[b][c][m] * P[b][n][m] + x[b][c][n]
//    Both A (v rows) and B (P rows, used as col-major k x n) are k-contiguous
//    -> direct row.col mma feed, no transpose.
//    grid (NN/128, CC/128, NB), 256 threads.
// ---------------------------------------------------------------------------
__global__ void __launch_bounds__(256)
k_out(const float* __restrict__ x, const float* __restrict__ gamma,
      float* __restrict__ out) {
    __shared__ uint32_t As[128 * BKP];
    __shared__ uint32_t Bs[128 * BKP];

    const int tid = threadIdx.x;
    const int n0 = blockIdx.x * 128;
    const int c0 = blockIdx.y * 128;
    const int b  = blockIdx.z;

    const int lane = tid & 31;
    const int gid  = lane >> 2;
    const int tig  = lane & 3;
    const int warp = tid >> 5;
    const int wm   = warp >> 1;
    const int wn   = warp & 1;

    float acc[2][8][4];
#pragma unroll
    for (int mf = 0; mf < 2; mf++)
#pragma unroll
        for (int nf = 0; nf < 8; nf++)
#pragma unroll
            for (int i = 0; i < 4; i++) acc[mf][nf][i] = 0.f;

    const float* vb = g_v + (size_t)b * CC * NN;
    const float* pb = g_s + (size_t)b * NN * NN;

    for (int k0 = 0; k0 < NN; k0 += TBK) {
        // A = v rows (m contiguous)
        for (int t = tid; t < 1024; t += 256) {
            int mm = t >> 3, k4 = (t & 7) << 2;
            float4 f = *(const float4*)(vb + (size_t)(c0 + mm) * NN + k0 + k4);
            uint32_t* p = &As[mm * BKP + k4];
            p[0] = f2tf32(f.x); p[1] = f2tf32(f.y);
            p[2] = f2tf32(f.z); p[3] = f2tf32(f.w);
        }
        // B columns = P rows (m contiguous)
        for (int t = tid; t < 1024; t += 256) {
            int nn = t >> 3, k4 = (t & 7) << 2;
            float4 f = *(const float4*)(pb + (size_t)(n0 + nn) * NN + k0 + k4);
            uint32_t* p = &Bs[nn * BKP + k4];
            p[0] = f2tf32(f.x); p[1] = f2tf32(f.y);
            p[2] = f2tf32(f.z); p[3] = f2tf32(f.w);
        }
        __syncthreads();
        mma_stage(As, Bs, acc, wm, wn, gid, tig);
        __syncthreads();
    }

    const float g = gamma[0];
    const float* xb = x + (size_t)b * CC * NN;
    float* ob = out + (size_t)b * CC * NN;
#pragma unroll
    for (int mf = 0; mf < 2; mf++)
#pragma unroll
        for (int nf = 0; nf < 8; nf++) {
            int c = c0 + wm * 32 + mf * 16 + gid;
            int n = n0 + wn * 64 + nf * 8 + tig * 2;
            size_t i0 = (size_t)c * NN + n;
            float2 x0 = *(const float2*)(xb + i0);
            *(float2*)(ob + i0) =
                make_float2(g * acc[mf][nf][0] + x0.x, g * acc[mf][nf][1] + x0.y);
            size_t i1 = i0 + (size_t)8 * NN;
            float2 x1 = *(const float2*)(xb + i1);
            *(float2*)(ob + i1) =
                make_float2(g * acc[mf][nf][2] + x1.x, g * acc[mf][nf][3] + x1.y);
        }
}

// ---------------------------------------------------------------------------
// Entry point: 5 sequential kernel launches, graph-capturable, no allocs.
// ---------------------------------------------------------------------------
extern "C" void kernel_launch(void* const* d_in, const int* in_sizes, int n_in,
                              void* d_out, int out_size) {
    const float* x     = (const float*)d_in[0];
    const float* Wq    = (const float*)d_in[1];
    const float* Wk    = (const float*)d_in[2];
    const float* Wv    = (const float*)d_in[3];
    const float* gamma = (const float*)d_in[4];
    float* out = (float*)d_out;

    k_qk<<<dim3(NN / BN, 1, NB), 256>>>(x, Wq, Wk);
    k_v <<<dim3(NN / 128, CC / 128, NB), 256>>>(x, Wv);
    k_s <<<dim3(NN / BN, NN / BM, NB), 256>>>();
    k_softmax<<<NB * NN, 256>>>();
    k_out<<<dim3(NN / 128, CC / 128, NB), 256>>>(x, gamma, out);
}

// round 10
// speedup vs baseline: 3.1281x; 1.6280x over previous
#include <cuda_runtime.h>
#include <cuda_bf16.h>
#include <cstdint>

// Problem constants
#define NB 16
#define CC 512
#define NN 2304      // 48*48
#define II 64        // inter channels

// fp32 tiling (k_qk)
#define BM 128
#define BN 128
#define BK 16
#define PAD 8

// tf32 mma tiling (k_v, k_out): 128x128 block, TBK=32 slabs, double-buffered
#define TBK 32
#define BKP 36                  // padded k-stride: 36 mod 32 = 4 -> conflict-free frag LDS
#define TILE_U (128 * BKP)      // uints per tensor per buffer (4608)
#define SMEM_VO (4 * TILE_U * 4)   // 2 tensors x 2 buffers x 4B = 73728 B

// k_s 3xTF32: whole K=64 in one stage, 4 tensors (A/B x hi/lo)
#define SKP 68                  // 68 mod 32 = 4 -> conflict-free frag LDS
#define STILE_U (128 * SKP)
#define SMEM_S (4 * STILE_U * 4)   // 139264 B

// ---------------------------------------------------------------------------
// Scratch (device globals: allocation-free per harness rules)
// ---------------------------------------------------------------------------
__device__ float g_qk[(size_t)NB * 128 * NN];       // rows 0..63 = q, 64..127 = k
__device__ float g_v [(size_t)NB * CC  * NN];       // v projection
__device__ float g_s [(size_t)NB * NN  * NN];       // attention logits / probs

// ---------------------------------------------------------------------------
// tf32 helpers
// ---------------------------------------------------------------------------
__device__ __forceinline__ uint32_t f2tf32(float f) {
    uint32_t r;
    asm("cvt.rna.tf32.f32 %0, %1;" : "=r"(r) : "f"(f));
    return r;
}

__device__ __forceinline__ void mma_tf32(float c[4], const uint32_t a[4],
                                         const uint32_t b[2]) {
    asm volatile(
        "mma.sync.aligned.m16n8k8.row.col.f32.tf32.tf32.f32 "
        "{%0,%1,%2,%3}, {%4,%5,%6,%7}, {%8,%9}, {%0,%1,%2,%3};"
        : "+f"(c[0]), "+f"(c[1]), "+f"(c[2]), "+f"(c[3])
        : "r"(a[0]), "r"(a[1]), "r"(a[2]), "r"(a[3]),
          "r"(b[0]), "r"(b[1]));
}

// mma mainloop stage for one TBK=32 slab resident in smem (stride BKP).
// Warp tile: 32 (m) x 64 (n) -> 2 m-frags x 8 n-frags.
__device__ __forceinline__ void mma_stage(const uint32_t* __restrict__ As,
                                          const uint32_t* __restrict__ Bs,
                                          float acc[2][8][4],
                                          int wm, int wn, int gid, int tig) {
#pragma unroll
    for (int ks = 0; ks < TBK; ks += 8) {
        uint32_t a[2][4], bf[8][2];
#pragma unroll
        for (int mf = 0; mf < 2; mf++) {
            int r = (wm * 32 + mf * 16 + gid) * BKP + ks + tig;
            a[mf][0] = As[r];
            a[mf][1] = As[r + 8 * BKP];
            a[mf][2] = As[r + 4];
            a[mf][3] = As[r + 8 * BKP + 4];
        }
#pragma unroll
        for (int nf = 0; nf < 8; nf++) {
            int r = (wn * 64 + nf * 8 + gid) * BKP + ks + tig;
            bf[nf][0] = Bs[r];
            bf[nf][1] = Bs[r + 4];
        }
#pragma unroll
        for (int mf = 0; mf < 2; mf++)
#pragma unroll
            for (int nf = 0; nf < 8; nf++)
                mma_tf32(acc[mf][nf], a[mf], bf[nf]);
    }
}

// ---------------------------------------------------------------------------
// fp32 8x8-microtile compute stage (k_qk)
// ---------------------------------------------------------------------------
__device__ __forceinline__ void mm_compute(const float (*As)[BM + PAD],
                                           const float (*Bs)[BN + PAD],
                                           float acc[8][8], int tr, int tc) {
#pragma unroll
    for (int kk = 0; kk < BK; kk++) {
        float ra[8], rb[8];
#pragma unroll
        for (int r = 0; r < 8; r++) ra[r] = As[kk][tr * 8 + r];
#pragma unroll
        for (int c = 0; c < 8; c++) rb[c] = Bs[kk][tc * 8 + c];
#pragma unroll
        for (int r = 0; r < 8; r++)
#pragma unroll
            for (int c = 0; c < 8; c++)
                acc[r][c] += ra[r] * rb[c];
    }
}

// ---------------------------------------------------------------------------
// 1) q/k projection (fp32 — feeds softmax, keep exact)
// ---------------------------------------------------------------------------
__global__ void __launch_bounds__(256)
k_qk(const float* __restrict__ x, const float* __restrict__ Wq,
     const float* __restrict__ Wk) {
    __shared__ float As[BK][BM + PAD];
    __shared__ float Bs[BK][BN + PAD];

    const int tid = threadIdx.x;
    const int n0 = blockIdx.x * BN;
    const int b  = blockIdx.z;
    const int tr = tid / 16, tc = tid % 16;

    float acc[8][8];
#pragma unroll
    for (int r = 0; r < 8; r++)
#pragma unroll
        for (int c = 0; c < 8; c++) acc[r][c] = 0.f;

    const float* xb = x + (size_t)b * CC * NN;

    for (int k0 = 0; k0 < CC; k0 += BK) {
        for (int i = tid; i < BM * BK; i += 256) {
            int mm = i / BK, kk = i % BK;
            const float* Wp = (mm < II) ? (Wq + (size_t)mm * CC)
                                        : (Wk + (size_t)(mm - II) * CC);
            As[kk][mm] = Wp[k0 + kk];
        }
        for (int i = tid; i < BK * BN; i += 256) {
            int kk = i / BN, nn = i % BN;
            Bs[kk][nn] = xb[(size_t)(k0 + kk) * NN + n0 + nn];
        }
        __syncthreads();
        mm_compute(As, Bs, acc, tr, tc);
        __syncthreads();
    }

    float* outb = g_qk + (size_t)b * 128 * NN;
#pragma unroll
    for (int r = 0; r < 8; r++) {
        size_t base = (size_t)(tr * 8 + r) * NN + n0 + tc * 8;
        *(float4*)(outb + base)     = make_float4(acc[r][0], acc[r][1], acc[r][2], acc[r][3]);
        *(float4*)(outb + base + 4) = make_float4(acc[r][4], acc[r][5], acc[r][6], acc[r][7]);
    }
}

// ---------------------------------------------------------------------------
// 2) v projection (tf32, register-double-buffered):
//    g_v[b][o][n] = sum_c Wv[o][c] * x[b][c][n]
// ---------------------------------------------------------------------------
__global__ void __launch_bounds__(256)
k_v(const float* __restrict__ x, const float* __restrict__ Wv) {
    extern __shared__ __align__(16) uint32_t sm[];
    uint32_t* Asb = sm;                  // [2][TILE_U]
    uint32_t* Bsb = sm + 2 * TILE_U;     // [2][TILE_U]

    const int tid = threadIdx.x;
    const int n0 = blockIdx.x * 128;
    const int m0 = blockIdx.y * 128;
    const int b  = blockIdx.z;

    const int lane = tid & 31;
    const int gid  = lane >> 2;
    const int tig  = lane & 3;
    const int warp = tid >> 5;
    const int wm   = warp >> 1;
    const int wn   = warp & 1;

    float acc[2][8][4];
#pragma unroll
    for (int mf = 0; mf < 2; mf++)
#pragma unroll
        for (int nf = 0; nf < 8; nf++)
#pragma unroll
            for (int i = 0; i < 4; i++) acc[mf][nf][i] = 0.f;

    const float* xb = x + (size_t)b * CC * NN;

    float4 ra[4];
    float  rb[16];

    auto load_tiles = [&](int k0) {
#pragma unroll
        for (int j = 0; j < 4; j++) {
            int t = tid + j * 256;
            int mm = t >> 3, k4 = (t & 7) << 2;
            ra[j] = *(const float4*)(Wv + (size_t)(m0 + mm) * CC + k0 + k4);
        }
#pragma unroll
        for (int j = 0; j < 16; j++) {
            int t = tid + j * 256;
            int kk = t >> 7, nn = t & 127;
            rb[j] = xb[(size_t)(k0 + kk) * NN + n0 + nn];
        }
    };
    auto store_tiles = [&](int buf) {
        uint32_t* As = Asb + buf * TILE_U;
        uint32_t* Bs = Bsb + buf * TILE_U;
#pragma unroll
        for (int j = 0; j < 4; j++) {
            int t = tid + j * 256;
            int mm = t >> 3, k4 = (t & 7) << 2;
            uint32_t* p = &As[mm * BKP + k4];
            p[0] = f2tf32(ra[j].x); p[1] = f2tf32(ra[j].y);
            p[2] = f2tf32(ra[j].z); p[3] = f2tf32(ra[j].w);
        }
#pragma unroll
        for (int j = 0; j < 16; j++) {
            int t = tid + j * 256;
            int kk = t >> 7, nn = t & 127;
            Bs[nn * BKP + kk] = f2tf32(rb[j]);
        }
    };

    load_tiles(0);
    store_tiles(0);
    __syncthreads();

    const int NIT = CC / TBK;   // 16
    for (int it = 0; it < NIT; it++) {
        int cur = it & 1;
        if (it + 1 < NIT) load_tiles((it + 1) * TBK);
        mma_stage(Asb + cur * TILE_U, Bsb + cur * TILE_U, acc, wm, wn, gid, tig);
        if (it + 1 < NIT) store_tiles(cur ^ 1);
        __syncthreads();
    }

    float* outb = g_v + (size_t)b * CC * NN;
#pragma unroll
    for (int mf = 0; mf < 2; mf++)
#pragma unroll
        for (int nf = 0; nf < 8; nf++) {
            int o = m0 + wm * 32 + mf * 16 + gid;
            int n = n0 + wn * 64 + nf * 8 + tig * 2;
            size_t i0 = (size_t)o * NN + n;
            *(float2*)(outb + i0) = make_float2(acc[mf][nf][0], acc[mf][nf][1]);
            size_t i1 = i0 + (size_t)8 * NN;
            *(float2*)(outb + i1) = make_float2(acc[mf][nf][2], acc[mf][nf][3]);
        }
}

// ---------------------------------------------------------------------------
// 3) logits via 3xTF32 (hi/lo split -> ~fp32 accuracy on the tensor pipe):
//    g_s[b][n][m] = sum_i q[b][i][n] * k[b][i][m],  K = 64 in ONE smem stage.
//    grid (NN/128 [key m], NN/128 [query n], NB)
// ---------------------------------------------------------------------------
__global__ void __launch_bounds__(256)
k_s() {
    extern __shared__ __align__(16) uint32_t sm[];
    uint32_t* Ah = sm;                   // query hi  [128][SKP]
    uint32_t* Al = Ah + STILE_U;         // query lo
    uint32_t* Bh = Al + STILE_U;         // key hi
    uint32_t* Bl = Bh + STILE_U;         // key lo

    const int tid = threadIdx.x;
    const int n0 = blockIdx.x * 128;     // key tile
    const int m0 = blockIdx.y * 128;     // query tile
    const int b  = blockIdx.z;

    const int lane = tid & 31;
    const int gid  = lane >> 2;
    const int tig  = lane & 3;
    const int warp = tid >> 5;
    const int wm   = warp >> 1;
    const int wn   = warp & 1;

    const float* qb = g_qk + (size_t)b * 128 * NN;   // rows [0,64): q
    const float* kb = qb + (size_t)II * NN;          // rows [64,128): k

    // Load + split A (query side): 128 (m) x 64 (k=i)
    for (int t = tid; t < 128 * II; t += 256) {
        int mm = t & 127, kk = t >> 7;
        float f = qb[(size_t)kk * NN + m0 + mm];
        uint32_t h = f2tf32(f);
        Ah[mm * SKP + kk] = h;
        Al[mm * SKP + kk] = f2tf32(f - __uint_as_float(h));
    }
    // Load + split B (key side)
    for (int t = tid; t < 128 * II; t += 256) {
        int nn = t & 127, kk = t >> 7;
        float f = kb[(size_t)kk * NN + n0 + nn];
        uint32_t h = f2tf32(f);
        Bh[nn * SKP + kk] = h;
        Bl[nn * SKP + kk] = f2tf32(f - __uint_as_float(h));
    }
    __syncthreads();

    float acc[2][8][4];
#pragma unroll
    for (int mf = 0; mf < 2; mf++)
#pragma unroll
        for (int nf = 0; nf < 8; nf++)
#pragma unroll
            for (int i = 0; i < 4; i++) acc[mf][nf][i] = 0.f;

#pragma unroll
    for (int ks = 0; ks < II; ks += 8) {
        uint32_t ah[2][4], al[2][4], bh[8][2], bl[8][2];
#pragma unroll
        for (int mf = 0; mf < 2; mf++) {
            int r = (wm * 32 + mf * 16 + gid) * SKP + ks + tig;
            ah[mf][0] = Ah[r];            al[mf][0] = Al[r];
            ah[mf][1] = Ah[r + 8 * SKP];  al[mf][1] = Al[r + 8 * SKP];
            ah[mf][2] = Ah[r + 4];        al[mf][2] = Al[r + 4];
            ah[mf][3] = Ah[r + 8 * SKP + 4]; al[mf][3] = Al[r + 8 * SKP + 4];
        }
#pragma unroll
        for (int nf = 0; nf < 8; nf++) {
            int r = (wn * 64 + nf * 8 + gid) * SKP + ks + tig;
            bh[nf][0] = Bh[r];     bl[nf][0] = Bl[r];
            bh[nf][1] = Bh[r + 4]; bl[nf][1] = Bl[r + 4];
        }
#pragma unroll
        for (int mf = 0; mf < 2; mf++)
#pragma unroll
            for (int nf = 0; nf < 8; nf++) {
                mma_tf32(acc[mf][nf], al[mf], bh[nf]);   // lo*hi
                mma_tf32(acc[mf][nf], ah[mf], bl[nf]);   // hi*lo
                mma_tf32(acc[mf][nf], ah[mf], bh[nf]);   // hi*hi
            }
    }

    float* sb = g_s + (size_t)b * NN * NN;
#pragma unroll
    for (int mf = 0; mf < 2; mf++)
#pragma unroll
        for (int nf = 0; nf < 8; nf++) {
            int qrow = m0 + wm * 32 + mf * 16 + gid;
            int kcol = n0 + wn * 64 + nf * 8 + tig * 2;
            size_t i0 = (size_t)qrow * NN + kcol;
            *(float2*)(sb + i0) = make_float2(acc[mf][nf][0], acc[mf][nf][1]);
            size_t i1 = i0 + (size_t)8 * NN;
            *(float2*)(sb + i1) = make_float2(acc[mf][nf][2], acc[mf][nf][3]);
        }
}

// ---------------------------------------------------------------------------
// 4) softmax over last dim of g_s, in place (DRAM roofline already)
// ---------------------------------------------------------------------------
__global__ void __launch_bounds__(256)
k_softmax() {
    const int tid = threadIdx.x;
    float* s = g_s + (size_t)blockIdx.x * NN;

    float v[9];
    float mx = -1e30f;
#pragma unroll
    for (int j = 0; j < 9; j++) {
        v[j] = s[tid + j * 256];
        mx = fmaxf(mx, v[j]);
    }
#pragma unroll
    for (int o = 16; o > 0; o >>= 1)
        mx = fmaxf(mx, __shfl_xor_sync(0xFFFFFFFFu, mx, o));

    __shared__ float redm[8];
    __shared__ float reds[8];
    if ((tid & 31) == 0) redm[tid >> 5] = mx;
    __syncthreads();
    float m2 = redm[0];
#pragma unroll
    for (int w = 1; w < 8; w++) m2 = fmaxf(m2, redm[w]);

    float sum = 0.f;
#pragma unroll
    for (int j = 0; j < 9; j++) {
        v[j] = __expf(v[j] - m2);
        sum += v[j];
    }
#pragma unroll
    for (int o = 16; o > 0; o >>= 1)
        sum += __shfl_xor_sync(0xFFFFFFFFu, sum, o);
    if ((tid & 31) == 0) reds[tid >> 5] = sum;
    __syncthreads();
    float tot = 0.f;
#pragma unroll
    for (int w = 0; w < 8; w++) tot += reds[w];

    const float inv = 1.0f / tot;
#pragma unroll
    for (int j = 0; j < 9; j++)
        s[tid + j * 256] = v[j] * inv;
}

// ---------------------------------------------------------------------------
// 5) out GEMM (tf32, register-double-buffered):
//    out[b][c][n] = gamma * sum_m v[b][c][m] * P[b][n][m] + x[b][c][n]
// ---------------------------------------------------------------------------
__global__ void __launch_bounds__(256)
k_out(const float* __restrict__ x, const float* __restrict__ gamma,
      float* __restrict__ out) {
    extern __shared__ __align__(16) uint32_t sm[];
    uint32_t* Asb = sm;
    uint32_t* Bsb = sm + 2 * TILE_U;

    const int tid = threadIdx.x;
    const int n0 = blockIdx.x * 128;
    const int c0 = blockIdx.y * 128;
    const int b  = blockIdx.z;

    const int lane = tid & 31;
    const int gid  = lane >> 2;
    const int tig  = lane & 3;
    const int warp = tid >> 5;
    const int wm   = warp >> 1;
    const int wn   = warp & 1;

    float acc[2][8][4];
#pragma unroll
    for (int mf = 0; mf < 2; mf++)
#pragma unroll
        for (int nf = 0; nf < 8; nf++)
#pragma unroll
            for (int i = 0; i < 4; i++) acc[mf][nf][i] = 0.f;

    const float* vb = g_v + (size_t)b * CC * NN;
    const float* pb = g_s + (size_t)b * NN * NN;

    float4 ra[4], rb4[4];

    auto load_tiles = [&](int k0) {
#pragma unroll
        for (int j = 0; j < 4; j++) {
            int t = tid + j * 256;
            int mm = t >> 3, k4 = (t & 7) << 2;
            ra[j]  = *(const float4*)(vb + (size_t)(c0 + mm) * NN + k0 + k4);
            rb4[j] = *(const float4*)(pb + (size_t)(n0 + mm) * NN + k0 + k4);
        }
    };
    auto store_tiles = [&](int buf) {
        uint32_t* As = Asb + buf * TILE_U;
        uint32_t* Bs = Bsb + buf * TILE_U;
#pragma unroll
        for (int j = 0; j < 4; j++) {
            int t = tid + j * 256;
            int mm = t >> 3, k4 = (t & 7) << 2;
            uint32_t* p = &As[mm * BKP + k4];
            p[0] = f2tf32(ra[j].x); p[1] = f2tf32(ra[j].y);
            p[2] = f2tf32(ra[j].z); p[3] = f2tf32(ra[j].w);
            uint32_t* q = &Bs[mm * BKP + k4];
            q[0] = f2tf32(rb4[j].x); q[1] = f2tf32(rb4[j].y);
            q[2] = f2tf32(rb4[j].z); q[3] = f2tf32(rb4[j].w);
        }
    };

    load_tiles(0);
    store_tiles(0);
    __syncthreads();

    const int NIT = NN / TBK;   // 72
    for (int it = 0; it < NIT; it++) {
        int cur = it & 1;
        if (it + 1 < NIT) load_tiles((it + 1) * TBK);
        mma_stage(Asb + cur * TILE_U, Bsb + cur * TILE_U, acc, wm, wn, gid, tig);
        if (it + 1 < NIT) store_tiles(cur ^ 1);
        __syncthreads();
    }

    const float g = gamma[0];
    const float* xb = x + (size_t)b * CC * NN;
    float* ob = out + (size_t)b * CC * NN;
#pragma unroll
    for (int mf = 0; mf < 2; mf++)
#pragma unroll
        for (int nf = 0; nf < 8; nf++) {
            int c = c0 + wm * 32 + mf * 16 + gid;
            int n = n0 + wn * 64 + nf * 8 + tig * 2;
            size_t i0 = (size_t)c * NN + n;
            float2 x0 = *(const float2*)(xb + i0);
            *(float2*)(ob + i0) =
                make_float2(g * acc[mf][nf][0] + x0.x, g * acc[mf][nf][1] + x0.y);
            size_t i1 = i0 + (size_t)8 * NN;
            float2 x1 = *(const float2*)(xb + i1);
            *(float2*)(ob + i1) =
                make_float2(g * acc[mf][nf][2] + x1.x, g * acc[mf][nf][3] + x1.y);
        }
}

// ---------------------------------------------------------------------------
// Entry point: 5 sequential kernel launches, graph-capturable, no allocs.
// cudaFuncSetAttribute is idempotent, not a stream op -> capture-safe.
// ---------------------------------------------------------------------------
extern "C" void kernel_launch(void* const* d_in, const int* in_sizes, int n_in,
                              void* d_out, int out_size) {
    const float* x     = (const float*)d_in[0];
    const float* Wq    = (const float*)d_in[1];
    const float* Wk    = (const float*)d_in[2];
    const float* Wv    = (const float*)d_in[3];
    const float* gamma = (const float*)d_in[4];
    float* out = (float*)d_out;

    cudaFuncSetAttribute(k_v,   cudaFuncAttributeMaxDynamicSharedMemorySize, SMEM_VO);
    cudaFuncSetAttribute(k_out, cudaFuncAttributeMaxDynamicSharedMemorySize, SMEM_VO);
    cudaFuncSetAttribute(k_s,   cudaFuncAttributeMaxDynamicSharedMemorySize, SMEM_S);

    k_qk<<<dim3(NN / BN, 1, NB), 256>>>(x, Wq, Wk);
    k_v <<<dim3(NN / 128, CC / 128, NB), 256, SMEM_VO>>>(x, Wv);
    k_s <<<dim3(NN / 128, NN / 128, NB), 256, SMEM_S>>>();
    k_softmax<<<NB * NN, 256>>>();
    k_out<<<dim3(NN / 128, CC / 128, NB), 256, SMEM_VO>>>(x, gamma, out);
}